// round 6
// baseline (speedup 1.0000x reference)
#include <cuda_runtime.h>
#include <math.h>

#define NPATCH 196
#define IPB    2                 // images per block
#define BLOCK  (IPB * 64)        // 2 warps per image

__global__ __launch_bounds__(BLOCK)
void quanv_fused_kernel(const float* __restrict__ x,
                        const float* __restrict__ emb_W,
                        const float* __restrict__ emb_b,
                        const float* __restrict__ q_params,
                        const float* __restrict__ lin_W,
                        const float* __restrict__ lin_b,
                        float* __restrict__ out,
                        int B)
{
    __shared__ float shalf[IPB][2][10];

    const int warp = threadIdx.x >> 5;
    const int lane = threadIdx.x & 31;
    const int img  = warp >> 1;        // image slot within block
    const int h    = warp & 1;         // which half of the patches
    const int b    = blockIdx.x * IPB + img;
    const bool valid = (b < B);
    const int bs = valid ? b : 0;      // safe pointer base; stores gated by `valid`

    // ---- uniform circuit constants (broadcast loads + MUFU) ----
    const float Kc0 = __cosf(q_params[0]);           // cos q0
    const float Kq1 = q_params[1];                   // q1
    float s4, c4;
    __sincosf(q_params[4], &s4, &c4);                // sin/cos q4
    const float Ks4 = s4 * __cosf(q_params[2]);      // sin q4 * cos q2
    const float Kc3 = __cosf(q_params[3]);           // cos q3

    const float4 W0 = __ldg((const float4*)(emb_W + 0));
    const float4 W1 = __ldg((const float4*)(emb_W + 4));
    const float4 W2 = __ldg((const float4*)(emb_W + 8));
    const float4 W3 = __ldg((const float4*)(emb_W + 12));
    const float4 eb = __ldg((const float4*)emb_b);

    const float*  xb  = x + bs * 784;
    const float4* lw4 = (const float4*)lin_W;   // lin_W[c*784 + 4*p] == lw4[c*196 + p]

    float acc[10];
#pragma unroll
    for (int c = 0; c < 10; c++) acc[c] = 0.f;

    // half h handles p = lane + 32h + 64k, k=0..2; half 0 also takes tail 192..195
#pragma unroll
    for (int k = 0; k < 4; k++) {
        const int p = lane + 32 * h + 64 * k;
        if (k == 3 && p >= NPATCH) break;   // only half 0, lanes 0..3 run k=3

        const int pr = p / 14, pc = p % 14;
        const float2 top = *(const float2*)(xb + (2 * pr) * 28 + 2 * pc);
        const float2 bot = *(const float2*)(xb + (2 * pr + 1) * 28 + 2 * pc);

        const float a0 = fmaf(top.x, W0.x, fmaf(top.y, W0.y, fmaf(bot.x, W0.z, fmaf(bot.y, W0.w, eb.x))));
        const float a1 = fmaf(top.x, W1.x, fmaf(top.y, W1.y, fmaf(bot.x, W1.z, fmaf(bot.y, W1.w, eb.y))));
        const float a2 = fmaf(top.x, W2.x, fmaf(top.y, W2.y, fmaf(bot.x, W2.z, fmaf(bot.y, W2.w, eb.z))));
        const float a3 = fmaf(top.x, W3.x, fmaf(top.y, W3.y, fmaf(bot.x, W3.z, fmaf(bot.y, W3.w, eb.w))));

        // closed-form <Z_w> of the 4-qubit circuit
        const float ca0  = __cosf(a0);
        const float ca1q = __cosf(a1 + Kq1);
        float sa2, ca2, sa3, ca3;
        __sincosf(a2, &sa2, &ca2);
        __sincosf(a3, &sa3, &ca3);

        const float e0 = Kc0 * ca0;
        const float e1 = e0 * ca1q;
        const float e2 = e1 * fmaf(c4, ca2, -Ks4 * sa2 * sa3);
        const float e3 = ca2 * (Kc3 * ca3);

        // accumulate partial logits (coalesced 512B per channel per round)
#pragma unroll
        for (int c = 0; c < 10; c++) {
            const float4 w = __ldg(&lw4[c * NPATCH + p]);
            acc[c] = fmaf(e0, w.x, fmaf(e1, w.y, fmaf(e2, w.z, fmaf(e3, w.w, acc[c]))));
        }
    }

    // ---- intra-warp xor-butterfly over this half's lanes ----
#pragma unroll
    for (int off = 16; off > 0; off >>= 1)
#pragma unroll
        for (int c = 0; c < 10; c++)
            acc[c] += __shfl_xor_sync(0xffffffffu, acc[c], off);

    if (lane < 10)
        shalf[img][h][lane] = acc[lane == 0 ? 0 : 0] * 0.f + acc[0] * 0.f + acc[lane]; // acc[lane]
    __syncthreads();

    // ---- half 0 finishes: combine halves, log_softmax, coalesced store ----
    if (h == 0 && lane < 10 && valid) {
        float lg[10];
#pragma unroll
        for (int c = 0; c < 10; c++)
            lg[c] = shalf[img][0][c] + shalf[img][1][c] + __ldg(&lin_b[c]);

        float mx = lg[0];
#pragma unroll
        for (int c = 1; c < 10; c++) mx = fmaxf(mx, lg[c]);
        float se = 0.f;
#pragma unroll
        for (int c = 0; c < 10; c++) se += __expf(lg[c] - mx);
        const float lse = mx + __logf(se);

        out[b * 10 + lane] = lg[lane] - lse;
    }
}

extern "C" void kernel_launch(void* const* d_in, const int* in_sizes, int n_in,
                              void* d_out, int out_size)
{
    const float* x        = (const float*)d_in[0];
    const float* emb_W    = (const float*)d_in[1];
    const float* emb_b    = (const float*)d_in[2];
    const float* q_params = (const float*)d_in[3];
    const float* lin_W    = (const float*)d_in[4];
    const float* lin_b    = (const float*)d_in[5];
    float* out = (float*)d_out;

    const int B = in_sizes[0] / 784;
    const int grid = (B + IPB - 1) / IPB;
    quanv_fused_kernel<<<grid, BLOCK>>>(x, emb_W, emb_b, q_params, lin_W, lin_b, out, B);
}